// round 11
// baseline (speedup 1.0000x reference)
#include <cuda_runtime.h>
#include <cuda_fp16.h>

// ---------------------------------------------------------------------------
// KPlaneRBFField on GB300 — round 11.
//  field kernel restructured: 4 points/warp, 8 lanes/point
//  (lane = p*8 + s*4 + q). Each plane sample loads the contiguous 128B
//  (x0|x1) row pair with ONE LDG.128 instruction per y-row (lanes span the
//  lines) -> wavefronts/pt drop ~52 -> ~28. Cross-lane x-side exchange via
//  4 SHFLs. lc0 i2-pairs and output rows get the same treatment.
// ---------------------------------------------------------------------------

#define NSIDE 64
#define MAXN  524288
#define NBUCK 32768
#define TP_POS 128

__device__ __half   g_planesTh[33030144];  // 66 MB transposed fp16 planes
__device__ __half   g_lc0h[8388608];       // 16.5 MB fp16 codes
__device__ unsigned g_hist[NBUCK];
__device__ unsigned g_blksum[32];
__device__ unsigned g_key[MAXN];
__device__ float4   g_spts[MAXN];          // sorted (xs0,xs1,xs2,pid)

__constant__ int c_plane_off[9] = {
    0,        524288,   1048576,
    1572864,  3670016,  5767168,
    7864320,  16252928, 24641536
};
__constant__ int c_blkCum[10] = {0,128,256,384,896,1408,1920,3968,6016,8064};
__constant__ int c_res[9]     = {128,128,128,256,256,256,512,512,512};

struct PrepArgs {
    const float* p[9];
    const float* lc0;
    const float* pts;
    const float* aabb;
    int n;
};

__device__ __forceinline__ unsigned spread3(unsigned x)
{
    x &= 0x3FF;
    x = (x | (x << 16)) & 0x30000FF;
    x = (x | (x << 8))  & 0x300F00F;
    x = (x | (x << 4))  & 0x30C30C3;
    x = (x | (x << 2))  & 0x9249249;
    return x;
}

// ---------------- k1: transpose + lc0 convert + histogram -------------------
__global__ void __launch_bounds__(256) prep_kernel(PrepArgs a)
{
    int b = blockIdx.x;
    int tid = threadIdx.x;

    if (b >= 16256) {                       // Morton histogram
        int i = (b - 16256) * 256 + tid;
        if (i >= a.n) return;
        float a0x = a.aabb[0], a0y = a.aabb[1], a0z = a.aabb[2];
        float a1x = a.aabb[3], a1y = a.aabb[4], a1z = a.aabb[5];
        float x = (a.pts[3 * i + 0] - a0x) * (2.0f / (a1x - a0x)) - 1.0f;
        float y = (a.pts[3 * i + 1] - a0y) * (2.0f / (a1y - a0y)) - 1.0f;
        float z = (a.pts[3 * i + 2] - a0z) * (2.0f / (a1z - a0z)) - 1.0f;
        int qx = min(max((int)((x + 1.0f) * 16.0f), 0), 31);
        int qy = min(max((int)((y + 1.0f) * 16.0f), 0), 31);
        int qz = min(max((int)((z + 1.0f) * 16.0f), 0), 31);
        unsigned key = (spread3(qx) << 2) | (spread3(qy) << 1) | spread3(qz);
        g_key[i] = key;
        atomicAdd(&g_hist[key], 1u);
        return;
    }
    if (b >= 8064) {                        // lc0 convert
        int i = (b - 8064) * 256 + tid;
        float4 v = __ldg((const float4*)a.lc0 + i);
        __half2 h0 = __floats2half2_rn(v.x, v.y);
        __half2 h1 = __floats2half2_rn(v.z, v.w);
        ((uint2*)g_lc0h)[i] = make_uint2(*(unsigned*)&h0, *(unsigned*)&h1);
        return;
    }

    // plane transpose
    __shared__ float tile[TP_POS][33];
    int pi = 0;
    #pragma unroll
    for (int i = 1; i < 9; i++) pi += (b >= c_blkCum[i]) ? 1 : 0;
    int r  = c_res[pi];
    int rr = r * r;
    int posBase = (b - c_blkCum[pi]) * TP_POS;
    const float4* src4 = (const float4*)a.p[pi];
    int rr4 = rr >> 2;
    int pb4 = posBase >> 2;

    #pragma unroll
    for (int it = 0; it < 4; it++) {
        int v  = tid + it * 256;
        int ch = v >> 5;
        int pv = v & 31;
        float4 val = src4[ch * rr4 + pb4 + pv];
        int p = pv << 2;
        tile[p + 0][ch] = val.x;
        tile[p + 1][ch] = val.y;
        tile[p + 2][ch] = val.z;
        tile[p + 3][ch] = val.w;
    }
    __syncthreads();

    uint2* dst2 = (uint2*)(g_planesTh + c_plane_off[pi]) + posBase * 8;
    #pragma unroll
    for (int it = 0; it < 4; it++) {
        int v  = tid + it * 256;
        int p  = v >> 3;
        int c4 = (v & 7) << 2;
        __half2 h0 = __floats2half2_rn(tile[p][c4 + 0], tile[p][c4 + 1]);
        __half2 h1 = __floats2half2_rn(tile[p][c4 + 2], tile[p][c4 + 3]);
        dst2[v] = make_uint2(*(unsigned*)&h0, *(unsigned*)&h1);
    }
}

// ---------------- k2: scan ---------------------------------------------------
__global__ void __launch_bounds__(1024) scan1_kernel()
{
    __shared__ unsigned wsum[32];
    int t = threadIdx.x;
    int lane = t & 31;
    int wid = t >> 5;
    int i = blockIdx.x * 1024 + t;
    unsigned v = g_hist[i];

    unsigned x = v;
    #pragma unroll
    for (int off = 1; off < 32; off <<= 1) {
        unsigned y = __shfl_up_sync(0xFFFFFFFFu, x, off);
        if (lane >= off) x += y;
    }
    if (lane == 31) wsum[wid] = x;
    __syncthreads();
    if (wid == 0) {
        unsigned w = wsum[lane];
        unsigned ww = w;
        #pragma unroll
        for (int off = 1; off < 32; off <<= 1) {
            unsigned y = __shfl_up_sync(0xFFFFFFFFu, ww, off);
            if (lane >= off) ww += y;
        }
        wsum[lane] = ww - w;
        if (lane == 31) g_blksum[blockIdx.x] = ww;
    }
    __syncthreads();
    g_hist[i] = x + wsum[wid] - v;
}

// ---------------- k3: scatter -------------------------------------------------
__global__ void scatter_kernel(const float* __restrict__ pts,
                               const float* __restrict__ aabb, int n)
{
    __shared__ unsigned blkoff[32];
    int t = threadIdx.x;
    if (t < 32) {
        unsigned v = g_blksum[t];
        unsigned x = v;
        #pragma unroll
        for (int off = 1; off < 32; off <<= 1) {
            unsigned y = __shfl_up_sync(0xFFFFFFFFu, x, off);
            if (t >= off) x += y;
        }
        blkoff[t] = x - v;
    }
    __syncthreads();

    int i = blockIdx.x * blockDim.x + t;
    if (i >= n) return;
    unsigned key = g_key[i];
    unsigned pos = atomicAdd(&g_hist[key], 1u) + blkoff[key >> 10];

    float a0x = aabb[0], a0y = aabb[1], a0z = aabb[2];
    float a1x = aabb[3], a1y = aabb[4], a1z = aabb[5];
    float xs0 = (pts[3 * i + 0] - a0x) * (2.0f / (a1x - a0x)) - 1.0f;
    float xs1 = (pts[3 * i + 1] - a0y) * (2.0f / (a1y - a0y)) - 1.0f;
    float xs2 = (pts[3 * i + 2] - a0z) * (2.0f / (a1z - a0z)) - 1.0f;
    g_spts[pos] = make_float4(xs0, xs1, xs2, __int_as_float(i));
}

__global__ void ident_kernel(const float* __restrict__ pts,
                             const float* __restrict__ aabb, int n)
{
    int i = blockIdx.x * blockDim.x + threadIdx.x;
    if (i >= n) return;
    float a0x = aabb[0], a0y = aabb[1], a0z = aabb[2];
    float a1x = aabb[3], a1y = aabb[4], a1z = aabb[5];
    float xs0 = (pts[3 * i + 0] - a0x) * (2.0f / (a1x - a0x)) - 1.0f;
    float xs1 = (pts[3 * i + 1] - a0y) * (2.0f / (a1y - a0y)) - 1.0f;
    float xs2 = (pts[3 * i + 2] - a0z) * (2.0f / (a1z - a0z)) - 1.0f;
    g_spts[i] = make_float4(xs0, xs1, xs2, __int_as_float(i));
}

// ---------------- fp16 helpers -----------------------------------------------
__device__ __forceinline__ __half2 u2h2(unsigned u)
{
    __half2 h;
    *(unsigned*)&h = u;
    return h;
}

// One bilinear sample. Lane (s,q) returns chans [8q+4s .. 8q+4s+4).
// Warp-wide: 2 LDG.128 (4 pts x 128B each) + 4 SHFL.
__device__ __forceinline__ float4 sampleP(const __half* __restrict__ T, int r,
                                          float u, float v, int k, int s)
{
    float fr = (float)(r - 1);
    float fx = (u + 1.0f) * 0.5f * fr;
    float fy = (v + 1.0f) * 0.5f * fr;
    float flx = fminf(fmaxf(floorf(fx), 0.0f), (float)(r - 2));
    float fly = fminf(fmaxf(floorf(fy), 0.0f), (float)(r - 2));
    float wx = fx - flx;
    float wy = fy - fly;
    int ix = (int)flx;
    int iy = (int)fly;

    // 128B region = texel(ix) 32ch | texel(ix+1) 32ch. Lane k grabs 16B.
    const uint4* b = (const uint4*)(T + ((iy * r + ix) << 5)) + k;
    uint4 R0 = __ldg(b);             // row y0
    uint4 R1 = __ldg(b + (r << 2));  // row y1

    // my comps for my chans (2s,2s+1); send comps (2(1-s), 2(1-s)+1)
    unsigned k0r0 = s ? R0.z : R0.x;
    unsigned k1r0 = s ? R0.w : R0.y;
    unsigned s0r0 = s ? R0.x : R0.z;
    unsigned s1r0 = s ? R0.y : R0.w;
    unsigned k0r1 = s ? R1.z : R1.x;
    unsigned k1r1 = s ? R1.w : R1.y;
    unsigned s0r1 = s ? R1.x : R1.z;
    unsigned s1r1 = s ? R1.y : R1.w;

    unsigned o0r0 = __shfl_xor_sync(0xFFFFFFFFu, s0r0, 4);
    unsigned o1r0 = __shfl_xor_sync(0xFFFFFFFFu, s1r0, 4);
    unsigned o0r1 = __shfl_xor_sync(0xFFFFFFFFu, s0r1, 4);
    unsigned o1r1 = __shfl_xor_sync(0xFFFFFFFFu, s1r1, 4);

    // x0 data = side-0 source, x1 data = side-1 source
    __half2 x0a0 = u2h2(s ? o0r0 : k0r0);
    __half2 x1a0 = u2h2(s ? k0r0 : o0r0);
    __half2 x0b0 = u2h2(s ? o1r0 : k1r0);
    __half2 x1b0 = u2h2(s ? k1r0 : o1r0);
    __half2 x0a1 = u2h2(s ? o0r1 : k0r1);
    __half2 x1a1 = u2h2(s ? k0r1 : o0r1);
    __half2 x0b1 = u2h2(s ? o1r1 : k1r1);
    __half2 x1b1 = u2h2(s ? k1r1 : o1r1);

    __half2 wx2 = __float2half2_rn(wx);
    __half2 ta = __hfma2(__hsub2(x1a0, x0a0), wx2, x0a0);  // row y0
    __half2 tb = __hfma2(__hsub2(x1b0, x0b0), wx2, x0b0);
    __half2 ua = __hfma2(__hsub2(x1a1, x0a1), wx2, x0a1);  // row y1
    __half2 ub = __hfma2(__hsub2(x1b1, x0b1), wx2, x0b1);

    float2 taf = __half22float2(ta);
    float2 tbf = __half22float2(tb);
    float2 uaf = __half22float2(ua);
    float2 ubf = __half22float2(ub);

    float4 o;
    o.x = taf.x + (uaf.x - taf.x) * wy;
    o.y = taf.y + (uaf.y - taf.y) * wy;
    o.z = tbf.x + (ubf.x - tbf.x) * wy;
    o.w = tbf.y + (ubf.y - tbf.y) * wy;
    return o;
}

// ---------------- k4: field kernel: 4 pts/warp, 8 lanes/pt -------------------
__global__ void __launch_bounds__(256, 5) field_kernel(
    const float* __restrict__ ks,
    const float* __restrict__ kpb,
    float* __restrict__ out,
    int npts)
{
    int gwarp = (int)((blockIdx.x * blockDim.x + threadIdx.x) >> 5);
    int lane  = threadIdx.x & 31;
    int p = lane >> 3;                 // point in warp: 0..3
    int k = lane & 7;                  // lane within point
    int s = k >> 2;                    // side (x-corner / i2-corner parity)
    int q = k & 3;                     // channel quad

    int slot = gwarp * 4 + p;
    bool valid = slot < npts;
    int cslot = valid ? slot : (npts - 1);

    float4 sp = __ldcs(&g_spts[cslot]);
    float xs0 = sp.x, xs1 = sp.y, xs2 = sp.z;
    int pid = __float_as_int(sp.w);

    float* outP = out + (size_t)pid * 128;
    const float4* kpb4 = (const float4*)kpb;
    int co = q * 8 + s * 4;            // channel offset of this lane's float4

    const int resArr[3] = {128, 256, 512};
    #pragma unroll
    for (int g = 0; g < 3; g++) {
        int r = resArr[g];
        float4 f0 = sampleP(g_planesTh + c_plane_off[g * 3 + 0], r, xs0, xs1, k, s);
        float4 f1 = sampleP(g_planesTh + c_plane_off[g * 3 + 1], r, xs0, xs2, k, s);
        float4 f2 = sampleP(g_planesTh + c_plane_off[g * 3 + 2], r, xs1, xs2, k, s);
        float4 bias = __ldg(kpb4 + g * 8 + q * 2 + s);
        float4 o;
        o.x = f0.x * f1.x * f2.x + bias.x;
        o.y = f0.y * f1.y * f2.y + bias.y;
        o.z = f0.z * f1.z * f2.z + bias.z;
        o.w = f0.w * f1.w * f2.w + bias.w;
        if (valid)
            __stcs((float4*)(outP + g * 32 + co), o);  // 1 instr = 4 full rows
    }

    // ---- RBF: 8 corners as 4 contiguous i2-pairs; lane handles corner ci2+s
    const float interval = 2.0f / (float)(NSIDE - 1);
    float c0f = fminf(fmaxf(floorf((xs0 + 1.0f) / interval), 0.0f), (float)(NSIDE - 2));
    float c1f = fminf(fmaxf(floorf((xs1 + 1.0f) / interval), 0.0f), (float)(NSIDE - 2));
    float c2f = fminf(fmaxf(floorf((xs2 + 1.0f) / interval), 0.0f), (float)(NSIDE - 2));
    int ci0 = (int)c0f, ci1 = (int)c1f, ci2 = (int)c2f;

    float myk2 = -1.0f + (float)(ci2 + s) * interval;
    float d2c = xs2 - myk2;
    float d2c2 = d2c * d2c;

    float acc[8] = {0.f, 0.f, 0.f, 0.f, 0.f, 0.f, 0.f, 0.f};
    float wsumOwn = 0.0f;
    #pragma unroll
    for (int m = 0; m < 4; m++) {
        int i0 = ci0 + (m >> 1);
        int i1 = ci1 + (m & 1);
        int idx0 = (i0 * NSIDE + i1) * NSIDE + ci2;     // pair base
        float sv = __ldg(&ks[idx0 + s]);
        float d0 = xs0 - (-1.0f + (float)i0 * interval);
        float d1 = xs1 - (-1.0f + (float)i1 * interval);
        float dist2 = d0 * d0 + d1 * d1 + d2c2;
        float phi = 1.0f / (1.0f + dist2 * sv * sv);
        wsumOwn += phi;
        // 128B pair region: corner(ci2) 32ch | corner(ci2+1) 32ch
        uint4 cu = __ldg((const uint4*)(g_lc0h + (idx0 << 5)) + k);
        float2 ca = __half22float2(u2h2(cu.x));
        float2 cb = __half22float2(u2h2(cu.y));
        float2 cc = __half22float2(u2h2(cu.z));
        float2 cd = __half22float2(u2h2(cu.w));
        acc[0] += phi * ca.x;  acc[1] += phi * ca.y;
        acc[2] += phi * cb.x;  acc[3] += phi * cb.y;
        acc[4] += phi * cc.x;  acc[5] += phi * cc.y;
        acc[6] += phi * cd.x;  acc[7] += phi * cd.y;
    }
    float wsum = wsumOwn + __shfl_xor_sync(0xFFFFFFFFu, wsumOwn, 4);

    // cross-side exchange: keep acc[4s..4s+4), receive other side's same chans
    float fin[4];
    #pragma unroll
    for (int j = 0; j < 4; j++) {
        float keep = acc[4 * s + j];
        float send = acc[4 * (1 - s) + j];
        float oth  = __shfl_xor_sync(0xFFFFFFFFu, send, 4);
        fin[j] = keep + oth;
    }

    float inv = 1.0f / (wsum + 1e-8f);
    float4 bias = __ldg(kpb4 + 24 + q * 2 + s);
    float4 o;
    o.x = fin[0] * inv + bias.x;
    o.y = fin[1] * inv + bias.y;
    o.z = fin[2] * inv + bias.z;
    o.w = fin[3] * inv + bias.w;
    if (valid)
        __stcs((float4*)(outP + 96 + co), o);
}

// ------------------------------ launcher ------------------------------------
extern "C" void kernel_launch(void* const* d_in, const int* in_sizes, int n_in,
                              void* d_out, int out_size)
{
    const float* pts  = (const float*)d_in[0];
    const float* aabb = (const float*)d_in[1];
    const float* lc0  = (const float*)d_in[11];
    const float* ks   = (const float*)d_in[12];
    const float* kpb  = (const float*)d_in[13];
    float* out = (float*)d_out;

    int npts = in_sizes[0] / 3;

    void* histPtr = nullptr;
    cudaGetSymbolAddress(&histPtr, g_hist);
    cudaMemsetAsync(histPtr, 0, NBUCK * sizeof(unsigned));

    PrepArgs a;
    for (int i = 0; i < 9; i++) a.p[i] = (const float*)d_in[2 + i];
    a.lc0 = lc0;
    a.pts = pts;
    a.aabb = aabb;
    a.n = npts;

    if (npts <= MAXN) {
        int histBlocks = (npts + 255) / 256;
        prep_kernel<<<16256 + histBlocks, 256>>>(a);
        scan1_kernel<<<32, 1024>>>();
        scatter_kernel<<<(npts + 255) / 256, 256>>>(pts, aabb, npts);
    } else {
        a.n = 0;
        prep_kernel<<<16256, 256>>>(a);
        ident_kernel<<<(npts + 255) / 256, 256>>>(pts, aabb, npts);
    }

    // 4 pts/warp, 8 warps/block -> 32 points per block
    int blocks = (npts + 31) / 32;
    field_kernel<<<blocks, 256>>>(ks, kpb, out, npts);
}

// round 12
// speedup vs baseline: 1.0233x; 1.0233x over previous
#include <cuda_runtime.h>
#include <cuda_fp16.h>

// ---------------------------------------------------------------------------
// KPlaneRBFField on GB300 — round 12.
//  R10 field structure (8 pts/warp, 4 lanes/pt — best so far) split into TWO
//  kernels (planes: chans 0..95, rbf: chans 96..127) to cut register
//  pressure and raise occupancy (R10 was capped at 4 blocks/SM by 64 regs
//  while L1tex-bound at 79.6%).
//  prep/scan/scatter unchanged from R10.
// ---------------------------------------------------------------------------

#define NSIDE 64
#define MAXN  524288
#define NBUCK 32768
#define TP_POS 128

__device__ __half   g_planesTh[33030144];  // 66 MB transposed fp16 planes
__device__ __half   g_lc0h[8388608];       // 16.5 MB fp16 codes
__device__ unsigned g_hist[NBUCK];
__device__ unsigned g_blksum[32];
__device__ unsigned g_key[MAXN];
__device__ float4   g_spts[MAXN];          // sorted (xs0,xs1,xs2,pid)

__constant__ int c_plane_off[9] = {
    0,        524288,   1048576,
    1572864,  3670016,  5767168,
    7864320,  16252928, 24641536
};
__constant__ int c_blkCum[10] = {0,128,256,384,896,1408,1920,3968,6016,8064};
__constant__ int c_res[9]     = {128,128,128,256,256,256,512,512,512};

struct PrepArgs {
    const float* p[9];
    const float* lc0;
    const float* pts;
    const float* aabb;
    int n;
};

__device__ __forceinline__ unsigned spread3(unsigned x)
{
    x &= 0x3FF;
    x = (x | (x << 16)) & 0x30000FF;
    x = (x | (x << 8))  & 0x300F00F;
    x = (x | (x << 4))  & 0x30C30C3;
    x = (x | (x << 2))  & 0x9249249;
    return x;
}

// ---------------- k1: transpose + lc0 convert + histogram -------------------
__global__ void __launch_bounds__(256) prep_kernel(PrepArgs a)
{
    int b = blockIdx.x;
    int tid = threadIdx.x;

    if (b >= 16256) {                       // Morton histogram
        int i = (b - 16256) * 256 + tid;
        if (i >= a.n) return;
        float a0x = a.aabb[0], a0y = a.aabb[1], a0z = a.aabb[2];
        float a1x = a.aabb[3], a1y = a.aabb[4], a1z = a.aabb[5];
        float x = (a.pts[3 * i + 0] - a0x) * (2.0f / (a1x - a0x)) - 1.0f;
        float y = (a.pts[3 * i + 1] - a0y) * (2.0f / (a1y - a0y)) - 1.0f;
        float z = (a.pts[3 * i + 2] - a0z) * (2.0f / (a1z - a0z)) - 1.0f;
        int qx = min(max((int)((x + 1.0f) * 16.0f), 0), 31);
        int qy = min(max((int)((y + 1.0f) * 16.0f), 0), 31);
        int qz = min(max((int)((z + 1.0f) * 16.0f), 0), 31);
        unsigned key = (spread3(qx) << 2) | (spread3(qy) << 1) | spread3(qz);
        g_key[i] = key;
        atomicAdd(&g_hist[key], 1u);
        return;
    }
    if (b >= 8064) {                        // lc0 convert
        int i = (b - 8064) * 256 + tid;
        float4 v = __ldg((const float4*)a.lc0 + i);
        __half2 h0 = __floats2half2_rn(v.x, v.y);
        __half2 h1 = __floats2half2_rn(v.z, v.w);
        ((uint2*)g_lc0h)[i] = make_uint2(*(unsigned*)&h0, *(unsigned*)&h1);
        return;
    }

    // plane transpose
    __shared__ float tile[TP_POS][33];
    int pi = 0;
    #pragma unroll
    for (int i = 1; i < 9; i++) pi += (b >= c_blkCum[i]) ? 1 : 0;
    int r  = c_res[pi];
    int rr = r * r;
    int posBase = (b - c_blkCum[pi]) * TP_POS;
    const float4* src4 = (const float4*)a.p[pi];
    int rr4 = rr >> 2;
    int pb4 = posBase >> 2;

    #pragma unroll
    for (int it = 0; it < 4; it++) {
        int v  = tid + it * 256;
        int ch = v >> 5;
        int pv = v & 31;
        float4 val = src4[ch * rr4 + pb4 + pv];
        int p = pv << 2;
        tile[p + 0][ch] = val.x;
        tile[p + 1][ch] = val.y;
        tile[p + 2][ch] = val.z;
        tile[p + 3][ch] = val.w;
    }
    __syncthreads();

    uint2* dst2 = (uint2*)(g_planesTh + c_plane_off[pi]) + posBase * 8;
    #pragma unroll
    for (int it = 0; it < 4; it++) {
        int v  = tid + it * 256;
        int p  = v >> 3;
        int c4 = (v & 7) << 2;
        __half2 h0 = __floats2half2_rn(tile[p][c4 + 0], tile[p][c4 + 1]);
        __half2 h1 = __floats2half2_rn(tile[p][c4 + 2], tile[p][c4 + 3]);
        dst2[v] = make_uint2(*(unsigned*)&h0, *(unsigned*)&h1);
    }
}

// ---------------- k2: scan ---------------------------------------------------
__global__ void __launch_bounds__(1024) scan1_kernel()
{
    __shared__ unsigned wsum[32];
    int t = threadIdx.x;
    int lane = t & 31;
    int wid = t >> 5;
    int i = blockIdx.x * 1024 + t;
    unsigned v = g_hist[i];

    unsigned x = v;
    #pragma unroll
    for (int off = 1; off < 32; off <<= 1) {
        unsigned y = __shfl_up_sync(0xFFFFFFFFu, x, off);
        if (lane >= off) x += y;
    }
    if (lane == 31) wsum[wid] = x;
    __syncthreads();
    if (wid == 0) {
        unsigned w = wsum[lane];
        unsigned ww = w;
        #pragma unroll
        for (int off = 1; off < 32; off <<= 1) {
            unsigned y = __shfl_up_sync(0xFFFFFFFFu, ww, off);
            if (lane >= off) ww += y;
        }
        wsum[lane] = ww - w;
        if (lane == 31) g_blksum[blockIdx.x] = ww;
    }
    __syncthreads();
    g_hist[i] = x + wsum[wid] - v;
}

// ---------------- k3: scatter -------------------------------------------------
__global__ void scatter_kernel(const float* __restrict__ pts,
                               const float* __restrict__ aabb, int n)
{
    __shared__ unsigned blkoff[32];
    int t = threadIdx.x;
    if (t < 32) {
        unsigned v = g_blksum[t];
        unsigned x = v;
        #pragma unroll
        for (int off = 1; off < 32; off <<= 1) {
            unsigned y = __shfl_up_sync(0xFFFFFFFFu, x, off);
            if (t >= off) x += y;
        }
        blkoff[t] = x - v;
    }
    __syncthreads();

    int i = blockIdx.x * blockDim.x + t;
    if (i >= n) return;
    unsigned key = g_key[i];
    unsigned pos = atomicAdd(&g_hist[key], 1u) + blkoff[key >> 10];

    float a0x = aabb[0], a0y = aabb[1], a0z = aabb[2];
    float a1x = aabb[3], a1y = aabb[4], a1z = aabb[5];
    float xs0 = (pts[3 * i + 0] - a0x) * (2.0f / (a1x - a0x)) - 1.0f;
    float xs1 = (pts[3 * i + 1] - a0y) * (2.0f / (a1y - a0y)) - 1.0f;
    float xs2 = (pts[3 * i + 2] - a0z) * (2.0f / (a1z - a0z)) - 1.0f;
    g_spts[pos] = make_float4(xs0, xs1, xs2, __int_as_float(i));
}

__global__ void ident_kernel(const float* __restrict__ pts,
                             const float* __restrict__ aabb, int n)
{
    int i = blockIdx.x * blockDim.x + threadIdx.x;
    if (i >= n) return;
    float a0x = aabb[0], a0y = aabb[1], a0z = aabb[2];
    float a1x = aabb[3], a1y = aabb[4], a1z = aabb[5];
    float xs0 = (pts[3 * i + 0] - a0x) * (2.0f / (a1x - a0x)) - 1.0f;
    float xs1 = (pts[3 * i + 1] - a0y) * (2.0f / (a1y - a0y)) - 1.0f;
    float xs2 = (pts[3 * i + 2] - a0z) * (2.0f / (a1z - a0z)) - 1.0f;
    g_spts[i] = make_float4(xs0, xs1, xs2, __int_as_float(i));
}

// ---------------- fp16 helpers ----------------------------------------------
__device__ __forceinline__ void h8tof8(uint4 u, float* f)
{
    float2 p;
    p = __half22float2(*(const __half2*)&u.x); f[0] = p.x; f[1] = p.y;
    p = __half22float2(*(const __half2*)&u.y); f[2] = p.x; f[3] = p.y;
    p = __half22float2(*(const __half2*)&u.z); f[4] = p.x; f[5] = p.y;
    p = __half22float2(*(const __half2*)&u.w); f[6] = p.x; f[7] = p.y;
}

// one bilinear sample of 8 channels: 4 LDG.128, x-lerp half2, y-lerp fp32.
__device__ __forceinline__ void sample8(const __half* __restrict__ T, int r,
                                        float u, float v, int c8, float* f)
{
    float fr = (float)(r - 1);
    float fx = (u + 1.0f) * 0.5f * fr;
    float fy = (v + 1.0f) * 0.5f * fr;
    float flx = fminf(fmaxf(floorf(fx), 0.0f), (float)(r - 2));
    float fly = fminf(fmaxf(floorf(fy), 0.0f), (float)(r - 2));
    float wx = fx - flx;
    float wy = fy - fly;
    int ix = (int)flx;
    int iy = (int)fly;
    const uint4* b = (const uint4*)(T + ((iy * r + ix) << 5)) + c8;
    int rs = r << 2;
    uint4 A = __ldg(b);
    uint4 B = __ldg(b + 4);
    uint4 C = __ldg(b + rs);
    uint4 D = __ldg(b + rs + 4);

    __half2 wx2 = __float2half2_rn(wx);
    const __half2* Ah = (const __half2*)&A;
    const __half2* Bh = (const __half2*)&B;
    const __half2* Ch = (const __half2*)&C;
    const __half2* Dh = (const __half2*)&D;
    #pragma unroll
    for (int i = 0; i < 4; i++) {
        __half2 t = __hfma2(__hsub2(Bh[i], Ah[i]), wx2, Ah[i]);
        __half2 o = __hfma2(__hsub2(Dh[i], Ch[i]), wx2, Ch[i]);
        float2 tf = __half22float2(t);
        float2 bf = __half22float2(o);
        f[2 * i + 0] = tf.x + (bf.x - tf.x) * wy;
        f[2 * i + 1] = tf.y + (bf.y - tf.y) * wy;
    }
}

// ---------------- k4a: planes kernel (chans 0..95) ---------------------------
__global__ void __launch_bounds__(256, 5) planes_kernel(
    const float* __restrict__ kpb,
    float* __restrict__ out,
    int npts)
{
    int gwarp = (int)((blockIdx.x * blockDim.x + threadIdx.x) >> 5);
    int lane  = threadIdx.x & 31;
    int pslot = lane >> 2;
    int c8    = lane & 3;

    int slot = gwarp * 8 + pslot;
    if (slot >= npts) return;

    float4 sp = __ldg(&g_spts[slot]);
    float xs0 = sp.x, xs1 = sp.y, xs2 = sp.z;
    int pid = __float_as_int(sp.w);

    float* outP = out + (size_t)pid * 128;
    const float4* kpb4 = (const float4*)kpb;

    const int resArr[3] = {128, 256, 512};
    #pragma unroll
    for (int s = 0; s < 3; s++) {
        int r = resArr[s];
        float f[8], g[8];
        sample8(g_planesTh + c_plane_off[s * 3 + 0], r, xs0, xs1, c8, f);
        sample8(g_planesTh + c_plane_off[s * 3 + 1], r, xs0, xs2, c8, g);
        #pragma unroll
        for (int j = 0; j < 8; j++) f[j] *= g[j];
        sample8(g_planesTh + c_plane_off[s * 3 + 2], r, xs1, xs2, c8, g);
        float4 bb0 = __ldg(kpb4 + s * 8 + c8 * 2);
        float4 bb1 = __ldg(kpb4 + s * 8 + c8 * 2 + 1);
        float4 o0, o1;
        o0.x = f[0] * g[0] + bb0.x;
        o0.y = f[1] * g[1] + bb0.y;
        o0.z = f[2] * g[2] + bb0.z;
        o0.w = f[3] * g[3] + bb0.w;
        o1.x = f[4] * g[4] + bb1.x;
        o1.y = f[5] * g[5] + bb1.y;
        o1.z = f[6] * g[6] + bb1.z;
        o1.w = f[7] * g[7] + bb1.w;
        float* op = outP + s * 32 + (c8 << 3);
        __stcs((float4*)op, o0);
        __stcs((float4*)(op + 4), o1);
    }
}

// ---------------- k4b: RBF kernel (chans 96..127) -----------------------------
__global__ void __launch_bounds__(256, 6) rbf_kernel(
    const float* __restrict__ ks,
    const float* __restrict__ kpb,
    float* __restrict__ out,
    int npts)
{
    int gwarp = (int)((blockIdx.x * blockDim.x + threadIdx.x) >> 5);
    int lane  = threadIdx.x & 31;
    int pslot = lane >> 2;
    int c8    = lane & 3;

    int slot = gwarp * 8 + pslot;
    if (slot >= npts) return;

    float4 sp = __ldg(&g_spts[slot]);
    float xs0 = sp.x, xs1 = sp.y, xs2 = sp.z;
    int pid = __float_as_int(sp.w);

    float* outP = out + (size_t)pid * 128;
    const float4* kpb4 = (const float4*)kpb;

    const float interval = 2.0f / (float)(NSIDE - 1);
    float c0f = fminf(fmaxf(floorf((xs0 + 1.0f) / interval), 0.0f), (float)(NSIDE - 2));
    float c1f = fminf(fmaxf(floorf((xs1 + 1.0f) / interval), 0.0f), (float)(NSIDE - 2));
    float c2f = fminf(fmaxf(floorf((xs2 + 1.0f) / interval), 0.0f), (float)(NSIDE - 2));
    int ci0 = (int)c0f, ci1 = (int)c1f, ci2 = (int)c2f;

    float acc[8] = {0.f, 0.f, 0.f, 0.f, 0.f, 0.f, 0.f, 0.f};
    float wsum = 0.0f;
    #pragma unroll
    for (int g = 0; g < 2; g++) {
        int idxA[4];
        float d2A[4];
        #pragma unroll
        for (int q = 0; q < 4; q++) {
            int k = g * 4 + q;
            int i0 = ci0 + ((k >> 2) & 1);
            int i1 = ci1 + ((k >> 1) & 1);
            int i2 = ci2 + (k & 1);
            idxA[q] = (i0 * NSIDE + i1) * NSIDE + i2;
            float d0 = xs0 - (-1.0f + (float)i0 * interval);
            float d1 = xs1 - (-1.0f + (float)i1 * interval);
            float d2 = xs2 - (-1.0f + (float)i2 * interval);
            d2A[q] = d0 * d0 + d1 * d1 + d2 * d2;
        }
        float svA[4];
        uint4 cuA[4];
        #pragma unroll
        for (int q = 0; q < 4; q++) {
            svA[q] = __ldg(&ks[idxA[q]]);
            cuA[q] = __ldg((const uint4*)(g_lc0h + (idxA[q] << 5)) + c8);
        }
        #pragma unroll
        for (int q = 0; q < 4; q++) {
            float phi = 1.0f / (1.0f + d2A[q] * svA[q] * svA[q]);
            wsum += phi;
            float code[8];
            h8tof8(cuA[q], code);
            #pragma unroll
            for (int j = 0; j < 8; j++) acc[j] += phi * code[j];
        }
    }
    float inv = 1.0f / (wsum + 1e-8f);
    float4 bb0 = __ldg(kpb4 + 24 + c8 * 2);
    float4 bb1 = __ldg(kpb4 + 24 + c8 * 2 + 1);
    float4 o0, o1;
    o0.x = acc[0] * inv + bb0.x;
    o0.y = acc[1] * inv + bb0.y;
    o0.z = acc[2] * inv + bb0.z;
    o0.w = acc[3] * inv + bb0.w;
    o1.x = acc[4] * inv + bb1.x;
    o1.y = acc[5] * inv + bb1.y;
    o1.z = acc[6] * inv + bb1.z;
    o1.w = acc[7] * inv + bb1.w;
    float* op = outP + 96 + (c8 << 3);
    __stcs((float4*)op, o0);
    __stcs((float4*)(op + 4), o1);
}

// ------------------------------ launcher ------------------------------------
extern "C" void kernel_launch(void* const* d_in, const int* in_sizes, int n_in,
                              void* d_out, int out_size)
{
    const float* pts  = (const float*)d_in[0];
    const float* aabb = (const float*)d_in[1];
    const float* lc0  = (const float*)d_in[11];
    const float* ks   = (const float*)d_in[12];
    const float* kpb  = (const float*)d_in[13];
    float* out = (float*)d_out;

    int npts = in_sizes[0] / 3;

    void* histPtr = nullptr;
    cudaGetSymbolAddress(&histPtr, g_hist);
    cudaMemsetAsync(histPtr, 0, NBUCK * sizeof(unsigned));

    PrepArgs a;
    for (int i = 0; i < 9; i++) a.p[i] = (const float*)d_in[2 + i];
    a.lc0 = lc0;
    a.pts = pts;
    a.aabb = aabb;
    a.n = npts;

    if (npts <= MAXN) {
        int histBlocks = (npts + 255) / 256;
        prep_kernel<<<16256 + histBlocks, 256>>>(a);
        scan1_kernel<<<32, 1024>>>();
        scatter_kernel<<<(npts + 255) / 256, 256>>>(pts, aabb, npts);
    } else {
        a.n = 0;
        prep_kernel<<<16256, 256>>>(a);
        ident_kernel<<<(npts + 255) / 256, 256>>>(pts, aabb, npts);
    }

    int blocks = (npts + 63) / 64;    // 8 pts/warp * 8 warps
    planes_kernel<<<blocks, 256>>>(kpb, out, npts);
    rbf_kernel<<<blocks, 256>>>(ks, kpb, out, npts);
}